// round 13
// baseline (speedup 1.0000x reference)
#include <cuda_runtime.h>
#include <cstdint>

// UltraTinyGRU fused, per-warp decoupled pipelines (no CTA barriers).
// B=4096, T=512, F=16, H=4. 128 blocks x 128 threads.
// Warp w owns rows 8w..8w+7: its lanes scan those rows (4 lanes/row) AND
// stage those rows' x via cp.async with per-warp commit groups. wait_group
// therefore covers exactly what the warp reads -> zero __syncthreads,
// zero cross-warp convoy. 3-buffer ring, issue-ahead-2, tail-aware waits.

#define GT 512
#define ROWS 32
#define THREADS 128
#define SSTEPS 4
#define NSTAGE (GT / SSTEPS)   // 128
#define XBUFS 3

__device__ __forceinline__ void cp_async16(void* smem_dst, const void* gmem_src) {
    unsigned int s = (unsigned int)__cvta_generic_to_shared(smem_dst);
    asm volatile("cp.async.cg.shared.global [%0], [%1], 16;\n"
                 :: "r"(s), "l"(gmem_src) : "memory");
}
__device__ __forceinline__ void cp_async_commit() {
    asm volatile("cp.async.commit_group;\n" ::: "memory");
}

__device__ __forceinline__ float tanh_fast(float x) {
    float y;
    asm("tanh.approx.f32 %0, %1;" : "=f"(y) : "f"(x));
    return y;
}

// ---- packed fp32x2 helpers ----
__device__ __forceinline__ double pack2(float lo, float hi) {
    double d;
    asm("mov.b64 %0, {%1, %2};" : "=d"(d) : "f"(lo), "f"(hi));
    return d;
}
__device__ __forceinline__ double fma2(double a, double b, double c) {
    double d;
    asm("fma.rn.f32x2 %0, %1, %2, %3;" : "=d"(d) : "d"(a), "d"(b), "d"(c));
    return d;
}
__device__ __forceinline__ double mul2(double a, double b) {
    double d;
    asm("mul.rn.f32x2 %0, %1, %2;" : "=d"(d) : "d"(a), "d"(b));
    return d;
}
__device__ __forceinline__ double add2(double a, double b) {
    double d;
    asm("add.rn.f32x2 %0, %1, %2;" : "=d"(d) : "d"(a), "d"(b));
    return d;
}
__device__ __forceinline__ float2 unpack2(double d) {
    float2 r;
    asm("mov.b64 {%0, %1}, %2;" : "=f"(r.x), "=f"(r.y) : "d"(d));
    return r;
}
__device__ __forceinline__ void pack_row(float4 v, float scale, double* dst) {
    dst[0] = pack2(v.x * scale, v.y * scale);
    dst[1] = pack2(v.z * scale, v.w * scale);
}
__device__ __forceinline__ float pdot16(const double2 q0, const double2 q1,
                                        const double2 q2, const double2 q3,
                                        const double* w, double bias) {
    double a = fma2(q0.x, w[0], bias);
    a = fma2(q0.y, w[1], a);
    a = fma2(q1.x, w[2], a);
    a = fma2(q1.y, w[3], a);
    double b = mul2(q2.x, w[4]);
    b = fma2(q2.y, w[5], b);
    b = fma2(q3.x, w[6], b);
    b = fma2(q3.y, w[7], b);
    const float2 u = unpack2(add2(a, b));
    return u.x + u.y;
}

__global__ __launch_bounds__(THREADS, 1)
void gru_fused(const float* __restrict__ x,
               const float* __restrict__ w_ih,
               const float* __restrict__ w_hh,
               const float* __restrict__ b_ih,
               const float* __restrict__ b_hh,
               const float* __restrict__ fc_w,
               const float* __restrict__ fc_b,
               float* __restrict__ out) {
    // [3 bufs][32 rows][17 float4]: 26112 B. Row stride 272B (17 float4,
    // odd 17 -> 8 consecutive rows hit 8 distinct bank groups: conflict-free).
    __shared__ float4 sx[XBUFS][ROWS][17];

    const int tid  = threadIdx.x;
    const int wid  = tid >> 5;
    const int lane = tid & 31;
    const int b0   = blockIdx.x * ROWS;
    const int row  = tid >> 2;      // 0..31 ; warp w holds rows 8w..8w+7
    const int j    = tid & 3;
    const int b    = b0 + row;

    // ---- packed input weights; r/z pre-halved (sigmoid->tanh fold) ----
    const float4* W = (const float4*)w_ih;
    double wrP[8], wzP[8], wnP[8];
#pragma unroll
    for (int q = 0; q < 4; q++) {
        pack_row(__ldg(&W[(j)     * 4 + q]), 0.5f, &wrP[q * 2]);
        pack_row(__ldg(&W[(4 + j) * 4 + q]), 0.5f, &wzP[q * 2]);
        pack_row(__ldg(&W[(8 + j) * 4 + q]), 1.0f, &wnP[q * 2]);
    }

    const float4* Wh = (const float4*)w_hh;
    float4 whr = __ldg(&Wh[j]);
    float4 whz = __ldg(&Wh[4 + j]);
    float4 whn = __ldg(&Wh[8 + j]);
    whr.x *= 0.5f; whr.y *= 0.5f; whr.z *= 0.5f; whr.w *= 0.5f;
    whz.x *= 0.5f; whz.y *= 0.5f; whz.z *= 0.5f; whz.w *= 0.5f;
    whn.x *= 0.5f; whn.y *= 0.5f; whn.z *= 0.5f; whn.w *= 0.5f;

    const float brh  = 0.5f * (__ldg(&b_ih[j])     + __ldg(&b_hh[j]));
    const float bzh  = 0.5f * (__ldg(&b_ih[4 + j]) + __ldg(&b_hh[4 + j]));
    const float bin  = __ldg(&b_ih[8 + j]);
    const float bhnh = 0.5f * __ldg(&b_hh[8 + j]);

    const double biasR = pack2(brh, 0.0f);
    const double biasZ = pack2(bzh, 0.0f);
    const double biasN = pack2(bin, 0.0f);

    // ---- per-warp staging: warp w stages ITS 8 rows x 4 steps x 64B ----
    // 128 chunks of 16B / 32 lanes = 4 cp.async per lane per stage.
    const float4* xbase = (const float4*)x;
    auto issue_stage = [&](int s) {
        const int buf = s % XBUFS;
#pragma unroll
        for (int k = 0; k < 4; k++) {
            const int c     = lane + k * 32;            // 0..127
            const int crow  = wid * 8 + (c >> 4);       // my warp's rows
            const int chunk = c & 15;
            const float4* src = xbase + ((size_t)(b0 + crow) * GT + s * SSTEPS) * 4 + chunk;
            cp_async16(&sx[buf][crow][chunk], src);
        }
        cp_async_commit();
    };

    issue_stage(0);
    issue_stage(1);
    issue_stage(2);

    float h0 = 0.f, h1 = 0.f, h2 = 0.f, h3 = 0.f;
    float hown = 0.f;   // this lane's h component

    for (int s = 0; s < NSTAGE; s++) {
        // tail-aware per-warp wait: pending after wait = {s+1, s+2} & valid
        if (s < NSTAGE - 2) {
            asm volatile("cp.async.wait_group 2;\n" ::: "memory");
        } else if (s == NSTAGE - 2) {
            asm volatile("cp.async.wait_group 1;\n" ::: "memory");
        } else {
            asm volatile("cp.async.wait_group 0;\n" ::: "memory");
        }
        __syncwarp();

        const double2* rx2 = (const double2*)&sx[s % XBUFS][row][0];
#pragma unroll
        for (int u = 0; u < SSTEPS; u++) {
            const double2 q0 = rx2[u * 4 + 0];
            const double2 q1 = rx2[u * 4 + 1];
            const double2 q2 = rx2[u * 4 + 2];
            const double2 q3 = rx2[u * 4 + 3];

            // input-side gate dots (off the recurrence chain)
            const float grC = pdot16(q0, q1, q2, q3, wrP, biasR);
            const float gzC = pdot16(q0, q1, q2, q3, wzP, biasZ);
            const float gnC = pdot16(q0, q1, q2, q3, wnP, biasN);

            // ---- recurrence chain ----
            float ar = fmaf(h0, whr.x, grC); ar = fmaf(h1, whr.y, ar);
            float cr = h2 * whr.z;           cr = fmaf(h3, whr.w, cr);
            const float arg_r = ar + cr;

            float az = fmaf(h0, whz.x, gzC); az = fmaf(h1, whz.y, az);
            float cz = h2 * whz.z;           cz = fmaf(h3, whz.w, cz);
            const float arg_z = az + cz;

            float an = fmaf(h0, whn.x, bhnh); an = fmaf(h1, whn.y, an);
            float cn = h2 * whn.z;            cn = fmaf(h3, whn.w, cn);
            const float ghn_h = an + cn;      // 0.5*(h.w_hh_n + b_hh_n)

            const float tr = tanh_fast(arg_r);
            const float tz = tanh_fast(arg_z);

            const float gnp  = gnC + ghn_h;
            const float narg = fmaf(tr, ghn_h, gnp);
            const float n    = tanh_fast(narg);

            // hn = n + z*(h-n),  z = 0.5 + 0.5*tz
            const float a   = fmaf(tz, 0.5f, 0.5f);   // parallel with hmn
            const float hmn = hown - n;
            const float hn  = fmaf(a, hmn, n);

            hown = hn;
            h0 = __shfl_sync(0xffffffffu, hn, 0, 4);
            h1 = __shfl_sync(0xffffffffu, hn, 1, 4);
            h2 = __shfl_sync(0xffffffffu, hn, 2, 4);
            h3 = __shfl_sync(0xffffffffu, hn, 3, 4);
        }

        if (s + 3 < NSTAGE) {
            issue_stage(s + 3);   // into buf (s+3)%3 = buf s%3, which this
        }                         // warp just finished reading (per-warp safe)
    }

    if (j == 0) {
        const float fw0 = __ldg(&fc_w[0]), fw1 = __ldg(&fc_w[1]);
        const float fw2 = __ldg(&fc_w[2]), fw3 = __ldg(&fc_w[3]);
        out[b] = (h0 * fw0 + h1 * fw1) + (h2 * fw2 + h3 * fw3) + __ldg(&fc_b[0]);
    }
}

extern "C" void kernel_launch(void* const* d_in, const int* in_sizes, int n_in,
                              void* d_out, int out_size) {
    const float* x    = (const float*)d_in[0];
    const float* w_ih = (const float*)d_in[1];
    const float* w_hh = (const float*)d_in[2];
    const float* b_ih = (const float*)d_in[3];
    const float* b_hh = (const float*)d_in[4];
    const float* fc_w = (const float*)d_in[5];
    const float* fc_b = (const float*)d_in[6];
    float* out = (float*)d_out;

    const int B = out_size;          // 4096
    const int blocks = B / ROWS;     // 128

    gru_fused<<<blocks, THREADS>>>(x, w_ih, w_hh, b_ih, b_hh, fc_w, fc_b, out);
}

// round 14
// speedup vs baseline: 1.6777x; 1.6777x over previous
#include <cuda_runtime.h>
#include <cstdint>

// UltraTinyGRU fused (R6 structure), leaner step body:
//  - r/z gates: packed f32x2 single-chain input dots that CONTINUE into the
//    packed hidden-side terms (one unpack+add total per gate)
//  - n gate: packed input dot + separate packed hidden dot (needed for r*ghn)
//  - 3 shfl.xor (bfly) instead of 4 broadcasts; per-lane permuted h-weights
// B=4096, T=512, F=16, H=4. 128 blocks x 128 threads, 1 row per quad.

#define GT 512
#define ROWS 32
#define THREADS 128
#define SSTEPS 8
#define NSTAGE (GT / SSTEPS)

__device__ __forceinline__ void cp_async16(void* smem_dst, const void* gmem_src) {
    unsigned int s = (unsigned int)__cvta_generic_to_shared(smem_dst);
    asm volatile("cp.async.cg.shared.global [%0], [%1], 16;\n"
                 :: "r"(s), "l"(gmem_src) : "memory");
}
__device__ __forceinline__ void cp_async_commit() {
    asm volatile("cp.async.commit_group;\n" ::: "memory");
}

__device__ __forceinline__ float tanh_fast(float x) {
    float y;
    asm("tanh.approx.f32 %0, %1;" : "=f"(y) : "f"(x));
    return y;
}

// ---- packed fp32x2 helpers ----
__device__ __forceinline__ double pack2(float lo, float hi) {
    double d;
    asm("mov.b64 %0, {%1, %2};" : "=d"(d) : "f"(lo), "f"(hi));
    return d;
}
__device__ __forceinline__ double fma2(double a, double b, double c) {
    double d;
    asm("fma.rn.f32x2 %0, %1, %2, %3;" : "=d"(d) : "d"(a), "d"(b), "d"(c));
    return d;
}
__device__ __forceinline__ float2 unpack2(double d) {
    float2 r;
    asm("mov.b64 {%0, %1}, %2;" : "=f"(r.x), "=f"(r.y) : "d"(d));
    return r;
}
__device__ __forceinline__ void pack_row(float4 v, float scale, double* dst) {
    dst[0] = pack2(v.x * scale, v.y * scale);
    dst[1] = pack2(v.z * scale, v.w * scale);
}

// 8-FFMA2 single chain over a 16-float row (bias-seeded, hoistable off-chain)
__device__ __forceinline__ double pchain16(const double2 q0, const double2 q1,
                                           const double2 q2, const double2 q3,
                                           const double* w, double bias) {
    double a = fma2(q0.x, w[0], bias);
    a = fma2(q0.y, w[1], a);
    a = fma2(q1.x, w[2], a);
    a = fma2(q1.y, w[3], a);
    a = fma2(q2.x, w[4], a);
    a = fma2(q2.y, w[5], a);
    a = fma2(q3.x, w[6], a);
    a = fma2(q3.y, w[7], a);
    return a;
}

__global__ __launch_bounds__(THREADS, 1)
void gru_fused(const float* __restrict__ x,
               const float* __restrict__ w_ih,
               const float* __restrict__ w_hh,
               const float* __restrict__ b_ih,
               const float* __restrict__ b_hh,
               const float* __restrict__ fc_w,
               const float* __restrict__ fc_b,
               float* __restrict__ out) {
    // [2 stages][32 rows][33 float4] -> 528B row stride (proven R6 layout)
    __shared__ float4 sx[2][ROWS][33];

    const int tid = threadIdx.x;
    const int b0  = blockIdx.x * ROWS;
    const int row = tid >> 2;
    const int j   = tid & 3;
    const int b   = b0 + row;

    // ---- packed input weights; r/z pre-halved (sigmoid->tanh fold) ----
    const float4* W = (const float4*)w_ih;
    double wrP[8], wzP[8], wnP[8];
#pragma unroll
    for (int q = 0; q < 4; q++) {
        pack_row(__ldg(&W[(j)     * 4 + q]), 0.5f, &wrP[q * 2]);
        pack_row(__ldg(&W[(4 + j) * 4 + q]), 0.5f, &wzP[q * 2]);
        pack_row(__ldg(&W[(8 + j) * 4 + q]), 1.0f, &wnP[q * 2]);
    }

    // ---- hidden-side weights, PERMUTED per lane for bfly ordering ----
    // v_m = h_{j^m}  =>  gate_row[j^m] multiplies v_m.
    // r/z/n all pre-halved (r,z: sigmoid fold; n: 0.5*ghn convention).
    const double whrP01 = pack2(0.5f * __ldg(&w_hh[(j)     * 4 + (j ^ 0)]),
                                0.5f * __ldg(&w_hh[(j)     * 4 + (j ^ 1)]));
    const double whrP23 = pack2(0.5f * __ldg(&w_hh[(j)     * 4 + (j ^ 2)]),
                                0.5f * __ldg(&w_hh[(j)     * 4 + (j ^ 3)]));
    const double whzP01 = pack2(0.5f * __ldg(&w_hh[(4 + j) * 4 + (j ^ 0)]),
                                0.5f * __ldg(&w_hh[(4 + j) * 4 + (j ^ 1)]));
    const double whzP23 = pack2(0.5f * __ldg(&w_hh[(4 + j) * 4 + (j ^ 2)]),
                                0.5f * __ldg(&w_hh[(4 + j) * 4 + (j ^ 3)]));
    const double whnP01 = pack2(0.5f * __ldg(&w_hh[(8 + j) * 4 + (j ^ 0)]),
                                0.5f * __ldg(&w_hh[(8 + j) * 4 + (j ^ 1)]));
    const double whnP23 = pack2(0.5f * __ldg(&w_hh[(8 + j) * 4 + (j ^ 2)]),
                                0.5f * __ldg(&w_hh[(8 + j) * 4 + (j ^ 3)]));

    const float brh  = 0.5f * (__ldg(&b_ih[j])     + __ldg(&b_hh[j]));
    const float bzh  = 0.5f * (__ldg(&b_ih[4 + j]) + __ldg(&b_hh[4 + j]));
    const float bin  = __ldg(&b_ih[8 + j]);
    const double biasR = pack2(brh, 0.0f);
    const double biasZ = pack2(bzh, 0.0f);
    const double biasN = pack2(bin, 0.0f);
    const double bhnP  = pack2(0.5f * __ldg(&b_hh[8 + j]), 0.0f);

    // ---- stage copy: 128 threads move 32 rows x 512B (R6-identical) ----
    const float4* xbase = (const float4*)x;
    auto issue_stage = [&](int s, int buf) {
#pragma unroll
        for (int it = 0; it < 8; it++) {
            const int c     = tid + it * THREADS;
            const int crow  = c >> 5;
            const int chunk = c & 31;
            const float4* src = xbase + ((size_t)(b0 + crow) * GT + s * SSTEPS) * 4 + chunk;
            cp_async16(&sx[buf][crow][chunk], src);
        }
        cp_async_commit();
    };

    issue_stage(0, 0);
    issue_stage(1, 1);

    // hidden state, bfly ordering: v0 = own component, v_m = h_{j^m}
    float v0 = 0.f, v1 = 0.f, v2 = 0.f, v3 = 0.f;

    for (int s = 0; s < NSTAGE; s++) {
        if (s == NSTAGE - 1) {
            asm volatile("cp.async.wait_group 0;\n" ::: "memory");
        } else {
            asm volatile("cp.async.wait_group 1;\n" ::: "memory");
        }
        __syncthreads();

        const double2* rx2 = (const double2*)&sx[s & 1][row][0];
#pragma unroll
        for (int u = 0; u < SSTEPS; u++) {
            const double2 q0 = rx2[u * 4 + 0];
            const double2 q1 = rx2[u * 4 + 1];
            const double2 q2 = rx2[u * 4 + 2];
            const double2 q3 = rx2[u * 4 + 3];

            // input-side packed chains (h-independent, hoistable)
            double aR = pchain16(q0, q1, q2, q3, wrP, biasR);
            double aZ = pchain16(q0, q1, q2, q3, wzP, biasZ);
            double aN = pchain16(q0, q1, q2, q3, wnP, biasN);

            // pack h (free-ish: 2 alu movs)
            const double hp01 = pack2(v0, v1);
            const double hp23 = pack2(v2, v3);

            // r/z: continue the SAME packed chain with hidden terms
            aR = fma2(hp01, whrP01, aR);
            aR = fma2(hp23, whrP23, aR);
            const float2 uR = unpack2(aR);
            const float arg_r = uR.x + uR.y;

            aZ = fma2(hp01, whzP01, aZ);
            aZ = fma2(hp23, whzP23, aZ);
            const float2 uZ = unpack2(aZ);
            const float arg_z = uZ.x + uZ.y;

            // n: input part and hidden part separate (r multiplies ghn)
            const float2 uN = unpack2(aN);
            const float gn = uN.x + uN.y;
            double nh = fma2(hp01, whnP01, bhnP);
            nh = fma2(hp23, whnP23, nh);
            const float2 uH = unpack2(nh);
            const float ghn_h = uH.x + uH.y;        // 0.5*(h.w_hh_n + b_hh_n)

            const float tr = tanh_fast(arg_r);
            const float tz = tanh_fast(arg_z);

            const float narg = fmaf(tr, ghn_h, gn + ghn_h);
            const float n    = tanh_fast(narg);

            // hn = n + z*(v0-n), z = 0.5 + 0.5*tz
            const float a   = fmaf(tz, 0.5f, 0.5f);
            const float hn  = fmaf(a, v0 - n, n);

            v0 = hn;
            v1 = __shfl_xor_sync(0xffffffffu, hn, 1, 4);
            v2 = __shfl_xor_sync(0xffffffffu, hn, 2, 4);
            v3 = __shfl_xor_sync(0xffffffffu, hn, 3, 4);
        }
        __syncthreads();

        if (s < NSTAGE - 2) {
            issue_stage(s + 2, s & 1);
        }
    }

    if (j == 0) {
        // lane 0: v0=h0, v1=h1, v2=h2, v3=h3
        const float fw0 = __ldg(&fc_w[0]), fw1 = __ldg(&fc_w[1]);
        const float fw2 = __ldg(&fc_w[2]), fw3 = __ldg(&fc_w[3]);
        out[b] = (v0 * fw0 + v1 * fw1) + (v2 * fw2 + v3 * fw3) + __ldg(&fc_b[0]);
    }
}

extern "C" void kernel_launch(void* const* d_in, const int* in_sizes, int n_in,
                              void* d_out, int out_size) {
    const float* x    = (const float*)d_in[0];
    const float* w_ih = (const float*)d_in[1];
    const float* w_hh = (const float*)d_in[2];
    const float* b_ih = (const float*)d_in[3];
    const float* b_hh = (const float*)d_in[4];
    const float* fc_w = (const float*)d_in[5];
    const float* fc_b = (const float*)d_in[6];
    float* out = (float*)d_out;

    const int B = out_size;          // 4096
    const int blocks = B / ROWS;     // 128

    gru_fused<<<blocks, THREADS>>>(x, w_ih, w_hh, b_ih, b_hh, fc_w, fc_b, out);
}